// round 14
// baseline (speedup 1.0000x reference)
#include <cuda_runtime.h>
#include <cuda_fp16.h>
#include <math.h>
#include <stdint.h>

// Problem dims (fixed)
#define BB   4
#define SS   2048
#define DD   256
#define HH   8
#define DKK  32
#define FF   1024
#define MTOT (BB*SS)   // 8192

#define SC2  0.25505654311f   // (1/sqrt(32)) * log2(e)
#define L2E  1.44269504089f

// -------- scratch (device globals), all f16 --------
__device__ __half g_xh[MTOT*DD];
__device__ __half g_wq[DD*DD], g_wk[DD*DD], g_wv[DD*DD], g_wo[DD*DD];
__device__ __half g_w1[DD*FF], g_w2[DD*FF], g_wout[FF*DD];
__device__ __half g_q[MTOT*DD];   // [B,H,S,DK], Q pre-scaled by SC2
__device__ __half g_k[MTOT*DD];
__device__ __half g_v[MTOT*DD];
__device__ __half g_attn[MTOT*DD]; // [B,S,D]
__device__ __half g_x1[MTOT*DD];
__device__ __half g_h[MTOT*FF];

// ---------------- helpers ----------------
__device__ __forceinline__ uint32_t pack_f16(float lo, float hi) {
    __half2 h = __floats2half2_rn(lo, hi);
    return *(uint32_t*)&h;
}
__device__ __forceinline__ float ex2f(float x) {
    float y;
    asm("ex2.approx.ftz.f32 %0, %1;" : "=f"(y) : "f"(x));
    return y;
}
__device__ __forceinline__ uint32_t ex2_h2(uint32_t x) {
    uint32_t y;
    asm("ex2.approx.f16x2 %0, %1;" : "=r"(y) : "r"(x));
    return y;
}
__device__ __forceinline__ uint32_t smem_u32(const void* p) {
    return (uint32_t)__cvta_generic_to_shared(p);
}
__device__ __forceinline__ void cp16(uint32_t dst, const void* src) {
    asm volatile("cp.async.cg.shared.global [%0], [%1], 16;" :: "r"(dst), "l"(src) : "memory");
}
#define CP_COMMIT()  asm volatile("cp.async.commit_group;" ::: "memory")
#define CP_WAIT(N)   asm volatile("cp.async.wait_group " #N ";" ::: "memory")
__device__ __forceinline__ void ldsm4(uint32_t& r0, uint32_t& r1, uint32_t& r2, uint32_t& r3,
                                      uint32_t a) {
    asm volatile("ldmatrix.sync.aligned.m8n8.x4.shared.b16 {%0,%1,%2,%3}, [%4];"
                 : "=r"(r0), "=r"(r1), "=r"(r2), "=r"(r3) : "r"(a));
}
__device__ __forceinline__ void ldsm4t(uint32_t& r0, uint32_t& r1, uint32_t& r2, uint32_t& r3,
                                       uint32_t a) {
    asm volatile("ldmatrix.sync.aligned.m8n8.x4.trans.shared.b16 {%0,%1,%2,%3}, [%4];"
                 : "=r"(r0), "=r"(r1), "=r"(r2), "=r"(r3) : "r"(a));
}
__device__ __forceinline__ void ldsm2t(uint32_t& r0, uint32_t& r1, uint32_t a) {
    asm volatile("ldmatrix.sync.aligned.m8n8.x2.trans.shared.b16 {%0,%1}, [%2];"
                 : "=r"(r0), "=r"(r1) : "r"(a));
}
__device__ __forceinline__ void mma_f16(float& d0, float& d1, float& d2, float& d3,
                                        uint32_t a0, uint32_t a1, uint32_t a2, uint32_t a3,
                                        uint32_t b0, uint32_t b1) {
    asm volatile(
        "mma.sync.aligned.m16n8k16.row.col.f32.f16.f16.f32 "
        "{%0,%1,%2,%3}, {%4,%5,%6,%7}, {%8,%9}, {%0,%1,%2,%3};"
        : "+f"(d0), "+f"(d1), "+f"(d2), "+f"(d3)
        : "r"(a0), "r"(a1), "r"(a2), "r"(a3), "r"(b0), "r"(b1));
}

#define ASR 40     // 80B row stride: LDSM conflict-free, 16B aligned
#define BSR 136    // 272B
#define BLR 264    // 528B (N=256 tile)
#define GSR 72     // 144B (N=64 tile)

#define NX   (MTOT*DD)
#define NW   (DD*DD)
#define NWF  (DD*FF)

// ============================================================================
// cvt: x + all weights fp32 -> f16 in ONE launch (launch #1).
// Total elems: NX + 4*NW + 3*NWF = 2097152 + 1048576 = 3145728 -> 3072 blocks.
// ============================================================================
__global__ __launch_bounds__(256)
void cvt_all(const float* __restrict__ x,
             const float* __restrict__ wq, const float* __restrict__ wk,
             const float* __restrict__ wv, const float* __restrict__ wo,
             const float* __restrict__ w1, const float* __restrict__ w2,
             const float* __restrict__ wout)
{
    long e = ((long)blockIdx.x * 256 + threadIdx.x) * 4;
    const float* src; __half* dst; long off;
    if      (e < NX)                  { src = x;    dst = g_xh;   off = e; }
    else if (e < NX + NW)             { src = wq;   dst = g_wq;   off = e - NX; }
    else if (e < NX + 2*NW)           { src = wk;   dst = g_wk;   off = e - NX - NW; }
    else if (e < NX + 3*NW)           { src = wv;   dst = g_wv;   off = e - NX - 2*NW; }
    else if (e < NX + 4*NW)           { src = wo;   dst = g_wo;   off = e - NX - 3*NW; }
    else if (e < NX + 4*NW + NWF)     { src = w1;   dst = g_w1;   off = e - NX - 4*NW; }
    else if (e < NX + 4*NW + 2*NWF)   { src = w2;   dst = g_w2;   off = e - NX - 4*NW - NWF; }
    else                              { src = wout; dst = g_wout; off = e - NX - 4*NW - 2*NWF; }
    float4 v = *(const float4*)&src[off];
    uint2 pk = make_uint2(pack_f16(v.x, v.y), pack_f16(v.z, v.w));
    *(uint2*)&dst[off] = pk;
}

// ============================================================================
// QKV GEMM (launch #2): block 128x128, BK=32, 3-stage cp.async pipeline.
// ============================================================================
__global__ __launch_bounds__(256, 2)
void gemm_qkv(void)
{
    __shared__ __half As[3][128 * ASR];
    __shared__ __half Bs[3][32 * BSR];

    const int which = blockIdx.x >> 1;
    const __half* A = g_xh;
    const __half* B = (which == 0) ? g_wq : (which == 1) ? g_wk : g_wv;
    __half* O = (which == 0) ? g_q : (which == 1) ? g_k : g_v;
    const int row0 = blockIdx.y * 128;
    const int col0 = (blockIdx.x & 1) * 128;

    const int t    = threadIdx.x;
    const int w    = t >> 5;
    const int lane = t & 31;
    const int g    = lane >> 2;
    const int q4   = lane & 3;
    const int wm   = w >> 1;
    const int wn   = w & 1;
    const int l15  = lane & 15;
    const int lhi  = (lane >> 4) << 3;

    float acc[2][8][4];
#pragma unroll
    for (int mi = 0; mi < 2; mi++)
#pragma unroll
        for (int ni = 0; ni < 8; ni++)
#pragma unroll
            for (int j = 0; j < 4; j++) acc[mi][ni][j] = 0.f;

    auto issue = [&](int st, int k0) {
#pragma unroll
        for (int i = 0; i < 2; i++) {
            int id = t + i * 256;
            { int r = id >> 2, c = (id & 3) << 3;
              cp16(smem_u32(&As[st][r * ASR + c]), &A[(size_t)(row0 + r) * DD + k0 + c]); }
            { int r = id >> 4, c = (id & 15) << 3;
              cp16(smem_u32(&Bs[st][r * BSR + c]), &B[(size_t)(k0 + r) * DD + col0 + c]); }
        }
    };

    issue(0, 0);  CP_COMMIT();
    issue(1, 32); CP_COMMIT();

    int p = 0;
    const int nIter = DD / 32;  // 8
    for (int it = 0; it < nIter; it++) {
        CP_WAIT(1);
        __syncthreads();
        int kn = (it + 2) * 32;
        if (kn < DD) { int st = p + 2; if (st >= 3) st -= 3; issue(st, kn); }
        CP_COMMIT();

        const uint32_t aBase = smem_u32(As[p]);
        const uint32_t bBase = smem_u32(Bs[p]);
#pragma unroll
        for (int ks = 0; ks < 2; ks++) {
            uint32_t a[2][4];
#pragma unroll
            for (int mi = 0; mi < 2; mi++)
                ldsm4(a[mi][0], a[mi][1], a[mi][2], a[mi][3],
                      aBase + (((32 * wm + 16 * mi + l15) * ASR) + 16 * ks + lhi) * 2);
            uint32_t b[8][2];
#pragma unroll
            for (int np = 0; np < 4; np++) {
                uint32_t r0, r1, r2, r3;
                ldsm4t(r0, r1, r2, r3,
                       bBase + (((16 * ks + l15) * BSR) + 64 * wn + 16 * np + lhi) * 2);
                b[2 * np][0] = r0; b[2 * np][1] = r1;
                b[2 * np + 1][0] = r2; b[2 * np + 1][1] = r3;
            }
#pragma unroll
            for (int mi = 0; mi < 2; mi++)
#pragma unroll
                for (int ni = 0; ni < 8; ni++)
                    mma_f16(acc[mi][ni][0], acc[mi][ni][1], acc[mi][ni][2], acc[mi][ni][3],
                            a[mi][0], a[mi][1], a[mi][2], a[mi][3],
                            b[ni][0], b[ni][1]);
        }
        if (++p == 3) p = 0;
    }

    const float mulf = (which == 0) ? SC2 : 1.f;
#pragma unroll
    for (int mi = 0; mi < 2; mi++) {
        int r = row0 + 32 * wm + 16 * mi + g;
#pragma unroll
        for (int ni = 0; ni < 8; ni++) {
            int c = col0 + 64 * wn + 8 * ni + 2 * q4;
#pragma unroll
            for (int half = 0; half < 2; half++) {
                int rr = r + half * 8;
                uint32_t pk = pack_f16(acc[mi][ni][2 * half] * mulf,
                                       acc[mi][ni][2 * half + 1] * mulf);
                int b  = rr >> 11;
                int s  = rr & 2047;
                int h  = c >> 5;
                int dk = c & 31;
                *(uint32_t*)&O[(((size_t)(b * HH + h) * SS) + s) * DKK + dk] = pk;
            }
        }
    }
}

// ============================================================================
// f16 flash attention (launch #3). NO-MAX softmax.
// q-tile 256 (8 warps x 32 rows), kv-tile 128 in a 3-stage cp.async ring,
// 32-key register chunks, K/V fragments shared across both m16 tiles.
// Row sums via ones-column mma (V col 32).
// ============================================================================
#define QSR 40
#define VSR 56   // cols 0-31 data, 32 = 1.0, 33-47 zero, pad to 56
__global__ __launch_bounds__(256, 2)
void attn_f16(void)
{
    __shared__ __half Qs[256 * QSR];       // 20.0 KB
    __shared__ __half Ks[3][128 * QSR];    // 30.0 KB
    __shared__ __half Vs[3][128 * VSR];    // 42.0 KB

    const int t    = threadIdx.x;
    const int w    = t >> 5;
    const int lane = t & 31;
    const int g    = lane >> 2;
    const int q4   = lane & 3;
    const int bh   = blockIdx.y;
    const int q0   = blockIdx.x * 256;
    const int l15  = lane & 15;
    const int lhi  = (lane >> 4) << 3;

    const __half* Qb = g_q + (size_t)bh * SS * DKK;
    const __half* Kb = g_k + (size_t)bh * SS * DKK;
    const __half* Vb = g_v + (size_t)bh * SS * DKK;

    auto issueKV = [&](int st, int kt) {
#pragma unroll
        for (int i = 0; i < 2; i++) {
            int id = t + i * 256;
            int r = id >> 2, c = (id & 3) << 3;
            cp16(smem_u32(&Ks[st][r * QSR + c]), &Kb[(size_t)(kt + r) * DKK + c]);
            cp16(smem_u32(&Vs[st][r * VSR + c]), &Vb[(size_t)(kt + r) * DKK + c]);
        }
    };

    // load Q tile (256x32): 4 uint4/thread
#pragma unroll
    for (int i = 0; i < 4; i++) {
        int id = t + i * 256;
        int r = id >> 2, c = (id & 3) << 3;
        *(uint4*)&Qs[r * QSR + c] = *(const uint4*)&Qb[(size_t)(q0 + r) * DKK + c];
    }

    // ones/zeros columns (32..47) of all 3 V buffers, once
    if (t < 128) {
        const uint32_t one0 = pack_f16(1.f, 0.f);
        uint4 z  = make_uint4(one0, 0u, 0u, 0u);
        uint4 z2 = make_uint4(0u, 0u, 0u, 0u);
#pragma unroll
        for (int st = 0; st < 3; st++) {
            *(uint4*)&Vs[st][t * VSR + 32] = z;
            *(uint4*)&Vs[st][t * VSR + 40] = z2;
        }
    }

    issueKV(0, 0);   CP_COMMIT();
    issueKV(1, 128); CP_COMMIT();
    __syncthreads();   // Q + ones visible

    const uint32_t qBase = smem_u32(Qs);
    uint32_t qf[2][2][4];
#pragma unroll
    for (int mi = 0; mi < 2; mi++)
#pragma unroll
        for (int ks = 0; ks < 2; ks++)
            ldsm4(qf[mi][ks][0], qf[mi][ks][1], qf[mi][ks][2], qf[mi][ks][3],
                  qBase + (((32 * w + 16 * mi + l15) * QSR) + 16 * ks + lhi) * 2);

    float o[2][4][4];
    float ol[2][4];
#pragma unroll
    for (int mi = 0; mi < 2; mi++) {
#pragma unroll
        for (int ni = 0; ni < 4; ni++)
#pragma unroll
            for (int j = 0; j < 4; j++) o[mi][ni][j] = 0.f;
#pragma unroll
        for (int j = 0; j < 4; j++) ol[mi][j] = 0.f;
    }

    int p = 0;
    for (int kt = 0; kt < SS; kt += 128) {
        CP_WAIT(1);
        __syncthreads();
        int ktn = kt + 256;
        if (ktn < SS) { int st = p + 2; if (st >= 3) st -= 3; issueKV(st, ktn); }
        CP_COMMIT();

        const uint32_t kBase = smem_u32(Ks[p]);
        const uint32_t vBase = smem_u32(Vs[p]);

#pragma unroll
        for (int sub = 0; sub < 4; sub++) {
            const int key0 = sub * 32;

            float s[2][4][4];
#pragma unroll
            for (int mi = 0; mi < 2; mi++)
#pragma unroll
                for (int ni = 0; ni < 4; ni++)
#pragma unroll
                    for (int j = 0; j < 4; j++) s[mi][ni][j] = 0.f;

#pragma unroll
            for (int ks = 0; ks < 2; ks++) {
#pragma unroll
                for (int np = 0; np < 2; np++) {
                    uint32_t r0, r1, r2, r3;
                    ldsm4(r0, r1, r2, r3,
                          kBase + (((key0 + 16 * np + l15) * QSR) + 16 * ks + lhi) * 2);
#pragma unroll
                    for (int mi = 0; mi < 2; mi++) {
                        mma_f16(s[mi][2 * np][0], s[mi][2 * np][1],
                                s[mi][2 * np][2], s[mi][2 * np][3],
                                qf[mi][ks][0], qf[mi][ks][1], qf[mi][ks][2], qf[mi][ks][3],
                                r0, r2);
                        mma_f16(s[mi][2 * np + 1][0], s[mi][2 * np + 1][1],
                                s[mi][2 * np + 1][2], s[mi][2 * np + 1][3],
                                qf[mi][ks][0], qf[mi][ks][1], qf[mi][ks][2], qf[mi][ks][3],
                                r1, r3);
                    }
                }
            }

            uint32_t pe0[2][4], pe1[2][4];
#pragma unroll
            for (int mi = 0; mi < 2; mi++)
#pragma unroll
                for (int ni = 0; ni < 4; ni++) {
                    pe0[mi][ni] = ex2_h2(pack_f16(s[mi][ni][0], s[mi][ni][1]));
                    pe1[mi][ni] = ex2_h2(pack_f16(s[mi][ni][2], s[mi][ni][3]));
                }

#pragma unroll
            for (int t4 = 0; t4 < 2; t4++) {
#pragma unroll
                for (int vh = 0; vh < 2; vh++) {
                    uint32_t r0, r1, r2, r3;
                    ldsm4t(r0, r1, r2, r3,
                           vBase + (((key0 + 16 * t4 + l15) * VSR) + 16 * vh + lhi) * 2);
#pragma unroll
                    for (int mi = 0; mi < 2; mi++) {
                        mma_f16(o[mi][2 * vh][0], o[mi][2 * vh][1],
                                o[mi][2 * vh][2], o[mi][2 * vh][3],
                                pe0[mi][2 * t4], pe1[mi][2 * t4],
                                pe0[mi][2 * t4 + 1], pe1[mi][2 * t4 + 1],
                                r0, r1);
                        mma_f16(o[mi][2 * vh + 1][0], o[mi][2 * vh + 1][1],
                                o[mi][2 * vh + 1][2], o[mi][2 * vh + 1][3],
                                pe0[mi][2 * t4], pe1[mi][2 * t4],
                                pe0[mi][2 * t4 + 1], pe1[mi][2 * t4 + 1],
                                r2, r3);
                    }
                }
                {   // ones column (n=8 B-frag via ldsm.x2, col base 32)
                    uint32_t r0, r1;
                    ldsm2t(r0, r1,
                           vBase + (((key0 + 16 * t4 + l15) * VSR) + 32) * 2);
#pragma unroll
                    for (int mi = 0; mi < 2; mi++)
                        mma_f16(ol[mi][0], ol[mi][1], ol[mi][2], ol[mi][3],
                                pe0[mi][2 * t4], pe1[mi][2 * t4],
                                pe0[mi][2 * t4 + 1], pe1[mi][2 * t4 + 1],
                                r0, r1);
                }
            }
        }
        if (++p == 3) p = 0;
    }

    const int b = bh >> 3;
    const int h = bh & 7;
#pragma unroll
    for (int mi = 0; mi < 2; mi++) {
        float l0 = __shfl_sync(0xffffffffu, ol[mi][0], lane & 28);
        float l1 = __shfl_sync(0xffffffffu, ol[mi][2], lane & 28);
        const int r0r = q0 + 32 * w + 16 * mi + g;
        float inv0 = 1.f / l0;
        float inv1 = 1.f / l1;
#pragma unroll
        for (int ni = 0; ni < 4; ni++) {
            int dk = 8 * ni + 2 * q4;
            size_t base0 = ((size_t)b * SS + r0r) * DD + h * DKK + dk;
            size_t base1 = ((size_t)b * SS + r0r + 8) * DD + h * DKK + dk;
            *(uint32_t*)&g_attn[base0] = pack_f16(o[mi][ni][0] * inv0, o[mi][ni][1] * inv0);
            *(uint32_t*)&g_attn[base1] = pack_f16(o[mi][ni][2] * inv1, o[mi][ni][3] * inv1);
        }
    }
}

// ============================================================================
// GEMM + residual + LayerNorm fused (launch #4 for FINAL=false -> profiled).
// Block 32(M) x 256(N), grid 256, 3-stage cp.async.
// FINAL=false -> write f16 (x1); FINAL=true -> write fp32 (d_out).
// ============================================================================
template<bool FINAL>
__global__ __launch_bounds__(256, 2)
void gemm_ln(const __half* __restrict__ A, const __half* __restrict__ B,
             const __half* __restrict__ resH, const float* __restrict__ gw,
             const float* __restrict__ bw, float* __restrict__ outF,
             __half* __restrict__ outH, int K)
{
    __shared__ __half As[3][32 * ASR];
    __shared__ __half Bs[3][32 * BLR];
    __shared__ float sRed[32][4];
    __shared__ float qRed[32][4];

    const int t    = threadIdx.x;
    const int w    = t >> 5;
    const int lane = t & 31;
    const int g    = lane >> 2;
    const int q4   = lane & 3;
    const int wm   = w >> 2;
    const int wn   = w & 3;
    const int l15  = lane & 15;
    const int lhi  = (lane >> 4) << 3;
    const int row0 = blockIdx.x * 32;

    float acc[8][4];
#pragma unroll
    for (int ni = 0; ni < 8; ni++)
#pragma unroll
        for (int j = 0; j < 4; j++) acc[ni][j] = 0.f;

    auto issue = [&](int st, int k0) {
        if (t < 128) {
            int r = t >> 2, c = (t & 3) << 3;
            cp16(smem_u32(&As[st][r * ASR + c]), &A[(size_t)(row0 + r) * K + k0 + c]);
        }
#pragma unroll
        for (int i = 0; i < 4; i++) {
            int id = t + i * 256;
            int r = id >> 5, c = (id & 31) << 3;
            cp16(smem_u32(&Bs[st][r * BLR + c]), &B[(size_t)(k0 + r) * DD + c]);
        }
    };

    issue(0, 0);  CP_COMMIT();
    issue(1, 32); CP_COMMIT();

    int p = 0;
    const int nIter = K / 32;
    for (int it = 0; it < nIter; it++) {
        CP_WAIT(1);
        __syncthreads();
        int kn = (it + 2) * 32;
        if (kn < K) { int st = p + 2; if (st >= 3) st -= 3; issue(st, kn); }
        CP_COMMIT();

        const uint32_t aBase = smem_u32(As[p]);
        const uint32_t bBase = smem_u32(Bs[p]);
#pragma unroll
        for (int ks = 0; ks < 2; ks++) {
            uint32_t a[4];
            ldsm4(a[0], a[1], a[2], a[3],
                  aBase + (((16 * wm + l15) * ASR) + 16 * ks + lhi) * 2);
            uint32_t b[8][2];
#pragma unroll
            for (int np = 0; np < 4; np++) {
                uint32_t r0, r1, r2, r3;
                ldsm4t(r0, r1, r2, r3,
                       bBase + (((16 * ks + l15) * BLR) + 64 * wn + 16 * np + lhi) * 2);
                b[2 * np][0] = r0; b[2 * np][1] = r1;
                b[2 * np + 1][0] = r2; b[2 * np + 1][1] = r3;
            }
#pragma unroll
            for (int ni = 0; ni < 8; ni++)
                mma_f16(acc[ni][0], acc[ni][1], acc[ni][2], acc[ni][3],
                        a[0], a[1], a[2], a[3], b[ni][0], b[ni][1]);
        }
        if (++p == 3) p = 0;
    }

    // ---- epilogue: +res (f16), row stats, LN, store ----
#pragma unroll
    for (int half = 0; half < 2; half++) {
        int rl = 16 * wm + g + 8 * half;
        int rr = row0 + rl;
        float s = 0.f, ss = 0.f;
#pragma unroll
        for (int ni = 0; ni < 8; ni++) {
            int c = 64 * wn + 8 * ni + 2 * q4;
            float2 rv = __half22float2(*(const __half2*)&resH[(size_t)rr * DD + c]);
            float v0 = acc[ni][2 * half] + rv.x;
            float v1 = acc[ni][2 * half + 1] + rv.y;
            acc[ni][2 * half] = v0;
            acc[ni][2 * half + 1] = v1;
            s += v0 + v1;
            ss += v0 * v0 + v1 * v1;
        }
        s  += __shfl_xor_sync(0xffffffffu, s, 1);
        s  += __shfl_xor_sync(0xffffffffu, s, 2);
        ss += __shfl_xor_sync(0xffffffffu, ss, 1);
        ss += __shfl_xor_sync(0xffffffffu, ss, 2);
        if (q4 == 0) { sRed[rl][wn] = s; qRed[rl][wn] = ss; }
    }
    __syncthreads();

    float mu_[2], rs_[2];
#pragma unroll
    for (int half = 0; half < 2; half++) {
        int rl = 16 * wm + g + 8 * half;
        float tot  = sRed[rl][0] + sRed[rl][1] + sRed[rl][2] + sRed[rl][3];
        float tot2 = qRed[rl][0] + qRed[rl][1] + qRed[rl][2] + qRed[rl][3];
        float mu = tot * (1.f / 256.f);
        mu_[half] = mu;
        rs_[half] = rsqrtf(tot2 * (1.f / 256.f) - mu * mu + 1e-5f);
    }

#pragma unroll
    for (int half = 0; half < 2; half++) {
        int rr = row0 + 16 * wm + g + 8 * half;
        float mu = mu_[half], rstd = rs_[half];
#pragma unroll
        for (int ni = 0; ni < 8; ni++) {
            int c = 64 * wn + 8 * ni + 2 * q4;
            float2 gp = *(const float2*)&gw[c];
            float2 bp = *(const float2*)&bw[c];
            float o0 = (acc[ni][2 * half]     - mu) * rstd * gp.x + bp.x;
            float o1 = (acc[ni][2 * half + 1] - mu) * rstd * gp.y + bp.y;
            if (FINAL) *(float2*)&outF[(size_t)rr * DD + c] = make_float2(o0, o1);
            else       *(uint32_t*)&outH[(size_t)rr * DD + c] = pack_f16(o0, o1);
        }
    }
}

// ============================================================================
// GLU GEMM: h = silu(A@W1) * (A@W2), block 128x64 dual-B, 3-stage cp.async.
// ============================================================================
__global__ __launch_bounds__(256, 2)
void gemm_glu(void)
{
    __shared__ __half As[3][128 * ASR];
    __shared__ __half Bs1[3][32 * GSR];
    __shared__ __half Bs2[3][32 * GSR];

    const int t    = threadIdx.x;
    const int w    = t >> 5;
    const int lane = t & 31;
    const int g    = lane >> 2;
    const int q4   = lane & 3;
    const int wm   = w >> 1;
    const int wn   = w & 1;
    const int l15  = lane & 15;
    const int lhi  = (lane >> 4) << 3;
    const int row0 = blockIdx.y * 128;
    const int col0 = blockIdx.x * 64;

    float ac1[2][4][4], ac2[2][4][4];
#pragma unroll
    for (int mi = 0; mi < 2; mi++)
#pragma unroll
        for (int ni = 0; ni < 4; ni++)
#pragma unroll
            for (int j = 0; j < 4; j++) { ac1[mi][ni][j] = 0.f; ac2[mi][ni][j] = 0.f; }

    auto issue = [&](int st, int k0) {
#pragma unroll
        for (int i = 0; i < 2; i++) {
            int id = t + i * 256;
            int r = id >> 2, c = (id & 3) << 3;
            cp16(smem_u32(&As[st][r * ASR + c]), &g_x1[(size_t)(row0 + r) * DD + k0 + c]);
        }
        { int r = t >> 3, c = (t & 7) << 3;
          cp16(smem_u32(&Bs1[st][r * GSR + c]), &g_w1[(size_t)(k0 + r) * FF + col0 + c]);
          cp16(smem_u32(&Bs2[st][r * GSR + c]), &g_w2[(size_t)(k0 + r) * FF + col0 + c]); }
    };

    issue(0, 0);  CP_COMMIT();
    issue(1, 32); CP_COMMIT();

    int p = 0;
    const int nIter = DD / 32;  // 8
    for (int it = 0; it < nIter; it++) {
        CP_WAIT(1);
        __syncthreads();
        int kn = (it + 2) * 32;
        if (kn < DD) { int st = p + 2; if (st >= 3) st -= 3; issue(st, kn); }
        CP_COMMIT();

        const uint32_t aBase  = smem_u32(As[p]);
        const uint32_t b1Base = smem_u32(Bs1[p]);
        const uint32_t b2Base = smem_u32(Bs2[p]);
#pragma unroll
        for (int ks = 0; ks < 2; ks++) {
            uint32_t a[2][4];
#pragma unroll
            for (int mi = 0; mi < 2; mi++)
                ldsm4(a[mi][0], a[mi][1], a[mi][2], a[mi][3],
                      aBase + (((32 * wm + 16 * mi + l15) * ASR) + 16 * ks + lhi) * 2);
            uint32_t b1[4][2], b2[4][2];
#pragma unroll
            for (int np = 0; np < 2; np++) {
                uint32_t r0, r1, r2, r3;
                ldsm4t(r0, r1, r2, r3,
                       b1Base + (((16 * ks + l15) * GSR) + 32 * wn + 16 * np + lhi) * 2);
                b1[2 * np][0] = r0; b1[2 * np][1] = r1;
                b1[2 * np + 1][0] = r2; b1[2 * np + 1][1] = r3;
                ldsm4t(r0, r1, r2, r3,
                       b2Base + (((16 * ks + l15) * GSR) + 32 * wn + 16 * np + lhi) * 2);
                b2[2 * np][0] = r0; b2[2 * np][1] = r1;
                b2[2 * np + 1][0] = r2; b2[2 * np + 1][1] = r3;
            }
#pragma unroll
            for (int mi = 0; mi < 2; mi++)
#pragma unroll
                for (int ni = 0; ni < 4; ni++) {
                    mma_f16(ac1[mi][ni][0], ac1[mi][ni][1], ac1[mi][ni][2], ac1[mi][ni][3],
                            a[mi][0], a[mi][1], a[mi][2], a[mi][3],
                            b1[ni][0], b1[ni][1]);
                    mma_f16(ac2[mi][ni][0], ac2[mi][ni][1], ac2[mi][ni][2], ac2[mi][ni][3],
                            a[mi][0], a[mi][1], a[mi][2], a[mi][3],
                            b2[ni][0], b2[ni][1]);
                }
        }
        if (++p == 3) p = 0;
    }

#pragma unroll
    for (int mi = 0; mi < 2; mi++) {
        int r = row0 + 32 * wm + 16 * mi + g;
#pragma unroll
        for (int ni = 0; ni < 4; ni++) {
            int c = col0 + 32 * wn + 8 * ni + 2 * q4;
#pragma unroll
            for (int half = 0; half < 2; half++) {
                int rr = r + half * 8;
                float u0 = ac1[mi][ni][2 * half], u1 = ac1[mi][ni][2 * half + 1];
                float v0 = ac2[mi][ni][2 * half], v1 = ac2[mi][ni][2 * half + 1];
                u0 = u0 / (1.f + ex2f(-L2E * u0));
                u1 = u1 / (1.f + ex2f(-L2E * u1));
                *(uint32_t*)&g_h[(size_t)rr * FF + c] = pack_f16(u0 * v0, u1 * v1);
            }
        }
    }
}

// ============================================================================
// Launch
// ============================================================================
extern "C" void kernel_launch(void* const* d_in, const int* in_sizes, int n_in,
                              void* d_out, int out_size)
{
    const float* x    = (const float*)d_in[0];
    const float* Wq   = (const float*)d_in[1];
    const float* Wk   = (const float*)d_in[2];
    const float* Wv   = (const float*)d_in[3];
    const float* Wo   = (const float*)d_in[4];
    const float* W1   = (const float*)d_in[5];
    const float* W2   = (const float*)d_in[6];
    const float* Wout = (const float*)d_in[7];
    const float* g1   = (const float*)d_in[8];
    const float* b1   = (const float*)d_in[9];
    const float* g2   = (const float*)d_in[10];
    const float* b2   = (const float*)d_in[11];

    __half *attn, *x1, *h, *xh, *wo_h, *wout_h;
    cudaGetSymbolAddress((void**)&attn,   g_attn);
    cudaGetSymbolAddress((void**)&x1,     g_x1);
    cudaGetSymbolAddress((void**)&h,      g_h);
    cudaGetSymbolAddress((void**)&xh,     g_xh);
    cudaGetSymbolAddress((void**)&wo_h,   g_wo);
    cudaGetSymbolAddress((void**)&wout_h, g_wout);

    // #1) x + weights fp32 -> f16, single pass
    cvt_all<<<3072, 256>>>(x, Wq, Wk, Wv, Wo, W1, W2, Wout);

    // #2) QKV projections -> f16 [B,H,S,DK] (Q pre-scaled by SC2)
    gemm_qkv<<<dim3(6, MTOT / 128), 256>>>();

    // #3) attention -> f16 [B,S,D]
    attn_f16<<<dim3(SS / 256, BB * HH), 256>>>();

    // #4) attn @ Wo + x (f16 res) -> LN -> x1 (f16)   [ncu slot]
    gemm_ln<false><<<MTOT / 32, 256>>>(attn, wo_h, xh, g1, b1, nullptr, x1, DD);

    // #5) GLU: h = silu(x1 @ W1) * (x1 @ W2), f16 out
    gemm_glu<<<dim3(FF / 64, MTOT / 128), 256>>>();

    // #6) h @ Wout + x1 (f16 res) -> LN -> out (fp32)
    gemm_ln<true><<<MTOT / 32, 256>>>(h, wout_h, x1, g2, b2, (float*)d_out, nullptr, FF);
}

// round 15
// speedup vs baseline: 1.0314x; 1.0314x over previous
#include <cuda_runtime.h>
#include <cuda_fp16.h>
#include <math.h>
#include <stdint.h>

// Problem dims (fixed)
#define BB   4
#define SS   2048
#define DD   256
#define HH   8
#define DKK  32
#define FF   1024
#define MTOT (BB*SS)   // 8192

#define SC2  0.25505654311f   // (1/sqrt(32)) * log2(e)
#define L2E  1.44269504089f

// -------- scratch (device globals), all f16 --------
__device__ __half g_xh[MTOT*DD];
__device__ __half g_wq[DD*DD], g_wk[DD*DD], g_wv[DD*DD], g_wo[DD*DD];
__device__ __half g_w1[DD*FF], g_w2[DD*FF], g_wout[FF*DD];
__device__ __half g_q[MTOT*DD];   // [B,H,S,DK], Q pre-scaled by SC2
__device__ __half g_k[MTOT*DD];
__device__ __half g_v[MTOT*DD];
__device__ __half g_attn[MTOT*DD]; // [B,S,D]
__device__ __half g_x1[MTOT*DD];
__device__ __half g_h[MTOT*FF];

// ---------------- helpers ----------------
__device__ __forceinline__ uint32_t pack_f16(float lo, float hi) {
    __half2 h = __floats2half2_rn(lo, hi);
    return *(uint32_t*)&h;
}
__device__ __forceinline__ float ex2f(float x) {
    float y;
    asm("ex2.approx.ftz.f32 %0, %1;" : "=f"(y) : "f"(x));
    return y;
}
__device__ __forceinline__ uint32_t ex2_h2(uint32_t x) {
    uint32_t y;
    asm("ex2.approx.f16x2 %0, %1;" : "=r"(y) : "r"(x));
    return y;
}
__device__ __forceinline__ uint32_t smem_u32(const void* p) {
    return (uint32_t)__cvta_generic_to_shared(p);
}
__device__ __forceinline__ void cp16(uint32_t dst, const void* src) {
    asm volatile("cp.async.cg.shared.global [%0], [%1], 16;" :: "r"(dst), "l"(src) : "memory");
}
#define CP_COMMIT()  asm volatile("cp.async.commit_group;" ::: "memory")
#define CP_WAIT(N)   asm volatile("cp.async.wait_group " #N ";" ::: "memory")
__device__ __forceinline__ void pdl_wait() {
    asm volatile("griddepcontrol.wait;" ::: "memory");
}
__device__ __forceinline__ void pdl_trigger() {
    asm volatile("griddepcontrol.launch_dependents;" ::: "memory");
}
__device__ __forceinline__ void ldsm4(uint32_t& r0, uint32_t& r1, uint32_t& r2, uint32_t& r3,
                                      uint32_t a) {
    asm volatile("ldmatrix.sync.aligned.m8n8.x4.shared.b16 {%0,%1,%2,%3}, [%4];"
                 : "=r"(r0), "=r"(r1), "=r"(r2), "=r"(r3) : "r"(a));
}
__device__ __forceinline__ void ldsm4t(uint32_t& r0, uint32_t& r1, uint32_t& r2, uint32_t& r3,
                                       uint32_t a) {
    asm volatile("ldmatrix.sync.aligned.m8n8.x4.trans.shared.b16 {%0,%1,%2,%3}, [%4];"
                 : "=r"(r0), "=r"(r1), "=r"(r2), "=r"(r3) : "r"(a));
}
__device__ __forceinline__ void ldsm2t(uint32_t& r0, uint32_t& r1, uint32_t a) {
    asm volatile("ldmatrix.sync.aligned.m8n8.x2.trans.shared.b16 {%0,%1}, [%2];"
                 : "=r"(r0), "=r"(r1) : "r"(a));
}
__device__ __forceinline__ void mma_f16(float& d0, float& d1, float& d2, float& d3,
                                        uint32_t a0, uint32_t a1, uint32_t a2, uint32_t a3,
                                        uint32_t b0, uint32_t b1) {
    asm volatile(
        "mma.sync.aligned.m16n8k16.row.col.f32.f16.f16.f32 "
        "{%0,%1,%2,%3}, {%4,%5,%6,%7}, {%8,%9}, {%0,%1,%2,%3};"
        : "+f"(d0), "+f"(d1), "+f"(d2), "+f"(d3)
        : "r"(a0), "r"(a1), "r"(a2), "r"(a3), "r"(b0), "r"(b1));
}

#define ASR 40     // 80B row stride: LDSM conflict-free, 16B aligned
#define BSR 136    // 272B
#define BLR 264    // 528B (N=256 tile)
#define GSR 72     // 144B (N=64 tile)

#define NX   (MTOT*DD)
#define NW   (DD*DD)
#define NWF  (DD*FF)

// ============================================================================
// cvt: x + all weights fp32 -> f16 in ONE launch (#1).
// ============================================================================
__global__ __launch_bounds__(256)
void cvt_all(const float* __restrict__ x,
             const float* __restrict__ wq, const float* __restrict__ wk,
             const float* __restrict__ wv, const float* __restrict__ wo,
             const float* __restrict__ w1, const float* __restrict__ w2,
             const float* __restrict__ wout)
{
    long e = ((long)blockIdx.x * 256 + threadIdx.x) * 4;
    const float* src; __half* dst; long off;
    if      (e < NX)                  { src = x;    dst = g_xh;   off = e; }
    else if (e < NX + NW)             { src = wq;   dst = g_wq;   off = e - NX; }
    else if (e < NX + 2*NW)           { src = wk;   dst = g_wk;   off = e - NX - NW; }
    else if (e < NX + 3*NW)           { src = wv;   dst = g_wv;   off = e - NX - 2*NW; }
    else if (e < NX + 4*NW)           { src = wo;   dst = g_wo;   off = e - NX - 3*NW; }
    else if (e < NX + 4*NW + NWF)     { src = w1;   dst = g_w1;   off = e - NX - 4*NW; }
    else if (e < NX + 4*NW + 2*NWF)   { src = w2;   dst = g_w2;   off = e - NX - 4*NW - NWF; }
    else                              { src = wout; dst = g_wout; off = e - NX - 4*NW - 2*NWF; }
    float4 v = *(const float4*)&src[off];
    uint2 pk = make_uint2(pack_f16(v.x, v.y), pack_f16(v.z, v.w));
    *(uint2*)&dst[off] = pk;
    pdl_trigger();
}

// ============================================================================
// QKV GEMM (#2): block 128x128, BK=32, 3-stage cp.async pipeline.
// ============================================================================
__global__ __launch_bounds__(256, 2)
void gemm_qkv(void)
{
    __shared__ __half As[3][128 * ASR];
    __shared__ __half Bs[3][32 * BSR];

    const int which = blockIdx.x >> 1;
    const __half* A = g_xh;
    const __half* B = (which == 0) ? g_wq : (which == 1) ? g_wk : g_wv;
    __half* O = (which == 0) ? g_q : (which == 1) ? g_k : g_v;
    const int row0 = blockIdx.y * 128;
    const int col0 = (blockIdx.x & 1) * 128;

    const int t    = threadIdx.x;
    const int w    = t >> 5;
    const int lane = t & 31;
    const int g    = lane >> 2;
    const int q4   = lane & 3;
    const int wm   = w >> 1;
    const int wn   = w & 1;
    const int l15  = lane & 15;
    const int lhi  = (lane >> 4) << 3;

    float acc[2][8][4];
#pragma unroll
    for (int mi = 0; mi < 2; mi++)
#pragma unroll
        for (int ni = 0; ni < 8; ni++)
#pragma unroll
            for (int j = 0; j < 4; j++) acc[mi][ni][j] = 0.f;

    auto issue = [&](int st, int k0) {
#pragma unroll
        for (int i = 0; i < 2; i++) {
            int id = t + i * 256;
            { int r = id >> 2, c = (id & 3) << 3;
              cp16(smem_u32(&As[st][r * ASR + c]), &A[(size_t)(row0 + r) * DD + k0 + c]); }
            { int r = id >> 4, c = (id & 15) << 3;
              cp16(smem_u32(&Bs[st][r * BSR + c]), &B[(size_t)(k0 + r) * DD + col0 + c]); }
        }
    };

    pdl_wait();   // all loads depend on cvt

    issue(0, 0);  CP_COMMIT();
    issue(1, 32); CP_COMMIT();

    int p = 0;
    const int nIter = DD / 32;  // 8
    for (int it = 0; it < nIter; it++) {
        CP_WAIT(1);
        __syncthreads();
        int kn = (it + 2) * 32;
        if (kn < DD) { int st = p + 2; if (st >= 3) st -= 3; issue(st, kn); }
        CP_COMMIT();

        const uint32_t aBase = smem_u32(As[p]);
        const uint32_t bBase = smem_u32(Bs[p]);
#pragma unroll
        for (int ks = 0; ks < 2; ks++) {
            uint32_t a[2][4];
#pragma unroll
            for (int mi = 0; mi < 2; mi++)
                ldsm4(a[mi][0], a[mi][1], a[mi][2], a[mi][3],
                      aBase + (((32 * wm + 16 * mi + l15) * ASR) + 16 * ks + lhi) * 2);
            uint32_t b[8][2];
#pragma unroll
            for (int np = 0; np < 4; np++) {
                uint32_t r0, r1, r2, r3;
                ldsm4t(r0, r1, r2, r3,
                       bBase + (((16 * ks + l15) * BSR) + 64 * wn + 16 * np + lhi) * 2);
                b[2 * np][0] = r0; b[2 * np][1] = r1;
                b[2 * np + 1][0] = r2; b[2 * np + 1][1] = r3;
            }
#pragma unroll
            for (int mi = 0; mi < 2; mi++)
#pragma unroll
                for (int ni = 0; ni < 8; ni++)
                    mma_f16(acc[mi][ni][0], acc[mi][ni][1], acc[mi][ni][2], acc[mi][ni][3],
                            a[mi][0], a[mi][1], a[mi][2], a[mi][3],
                            b[ni][0], b[ni][1]);
        }
        if (++p == 3) p = 0;
    }

    const float mulf = (which == 0) ? SC2 : 1.f;
#pragma unroll
    for (int mi = 0; mi < 2; mi++) {
        int r = row0 + 32 * wm + 16 * mi + g;
#pragma unroll
        for (int ni = 0; ni < 8; ni++) {
            int c = col0 + 64 * wn + 8 * ni + 2 * q4;
#pragma unroll
            for (int half = 0; half < 2; half++) {
                int rr = r + half * 8;
                uint32_t pk = pack_f16(acc[mi][ni][2 * half] * mulf,
                                       acc[mi][ni][2 * half + 1] * mulf);
                int b  = rr >> 11;
                int s  = rr & 2047;
                int h  = c >> 5;
                int dk = c & 31;
                *(uint32_t*)&O[(((size_t)(b * HH + h) * SS) + s) * DKK + dk] = pk;
            }
        }
    }
    pdl_trigger();
}

// ============================================================================
// f16 flash attention (#3). NO-MAX softmax. q-tile 256 (8 warps x 32 rows),
// kv-tile 128 3-stage cp.async ring, K/V frags shared across both m16 tiles.
// Row sums via ones-column mma (V col 32).
// ============================================================================
#define QSR 40
#define VSR 56
__global__ __launch_bounds__(256, 2)
void attn_f16(void)
{
    __shared__ __half Qs[256 * QSR];
    __shared__ __half Ks[3][128 * QSR];
    __shared__ __half Vs[3][128 * VSR];

    const int t    = threadIdx.x;
    const int w    = t >> 5;
    const int lane = t & 31;
    const int g    = lane >> 2;
    const int q4   = lane & 3;
    const int bh   = blockIdx.y;
    const int q0   = blockIdx.x * 256;
    const int l15  = lane & 15;
    const int lhi  = (lane >> 4) << 3;

    const __half* Qb = g_q + (size_t)bh * SS * DKK;
    const __half* Kb = g_k + (size_t)bh * SS * DKK;
    const __half* Vb = g_v + (size_t)bh * SS * DKK;

    auto issueKV = [&](int st, int kt) {
#pragma unroll
        for (int i = 0; i < 2; i++) {
            int id = t + i * 256;
            int r = id >> 2, c = (id & 3) << 3;
            cp16(smem_u32(&Ks[st][r * QSR + c]), &Kb[(size_t)(kt + r) * DKK + c]);
            cp16(smem_u32(&Vs[st][r * VSR + c]), &Vb[(size_t)(kt + r) * DKK + c]);
        }
    };

    // independent prologue: ones/zeros columns (32..47) of all 3 V buffers
    if (t < 128) {
        const uint32_t one0 = pack_f16(1.f, 0.f);
        uint4 z  = make_uint4(one0, 0u, 0u, 0u);
        uint4 z2 = make_uint4(0u, 0u, 0u, 0u);
#pragma unroll
        for (int st = 0; st < 3; st++) {
            *(uint4*)&Vs[st][t * VSR + 32] = z;
            *(uint4*)&Vs[st][t * VSR + 40] = z2;
        }
    }

    pdl_wait();   // q/k/v written by gemm_qkv

    // load Q tile (256x32): 4 uint4/thread
#pragma unroll
    for (int i = 0; i < 4; i++) {
        int id = t + i * 256;
        int r = id >> 2, c = (id & 3) << 3;
        *(uint4*)&Qs[r * QSR + c] = *(const uint4*)&Qb[(size_t)(q0 + r) * DKK + c];
    }

    issueKV(0, 0);   CP_COMMIT();
    issueKV(1, 128); CP_COMMIT();
    __syncthreads();   // Q + ones visible

    const uint32_t qBase = smem_u32(Qs);
    uint32_t qf[2][2][4];
#pragma unroll
    for (int mi = 0; mi < 2; mi++)
#pragma unroll
        for (int ks = 0; ks < 2; ks++)
            ldsm4(qf[mi][ks][0], qf[mi][ks][1], qf[mi][ks][2], qf[mi][ks][3],
                  qBase + (((32 * w + 16 * mi + l15) * QSR) + 16 * ks + lhi) * 2);

    float o[2][4][4];
    float ol[2][4];
#pragma unroll
    for (int mi = 0; mi < 2; mi++) {
#pragma unroll
        for (int ni = 0; ni < 4; ni++)
#pragma unroll
            for (int j = 0; j < 4; j++) o[mi][ni][j] = 0.f;
#pragma unroll
        for (int j = 0; j < 4; j++) ol[mi][j] = 0.f;
    }

    int p = 0;
    for (int kt = 0; kt < SS; kt += 128) {
        CP_WAIT(1);
        __syncthreads();
        int ktn = kt + 256;
        if (ktn < SS) { int st = p + 2; if (st >= 3) st -= 3; issueKV(st, ktn); }
        CP_COMMIT();

        const uint32_t kBase = smem_u32(Ks[p]);
        const uint32_t vBase = smem_u32(Vs[p]);

#pragma unroll
        for (int sub = 0; sub < 4; sub++) {
            const int key0 = sub * 32;

            float s[2][4][4];
#pragma unroll
            for (int mi = 0; mi < 2; mi++)
#pragma unroll
                for (int ni = 0; ni < 4; ni++)
#pragma unroll
                    for (int j = 0; j < 4; j++) s[mi][ni][j] = 0.f;

#pragma unroll
            for (int ks = 0; ks < 2; ks++) {
#pragma unroll
                for (int np = 0; np < 2; np++) {
                    uint32_t r0, r1, r2, r3;
                    ldsm4(r0, r1, r2, r3,
                          kBase + (((key0 + 16 * np + l15) * QSR) + 16 * ks + lhi) * 2);
#pragma unroll
                    for (int mi = 0; mi < 2; mi++) {
                        mma_f16(s[mi][2 * np][0], s[mi][2 * np][1],
                                s[mi][2 * np][2], s[mi][2 * np][3],
                                qf[mi][ks][0], qf[mi][ks][1], qf[mi][ks][2], qf[mi][ks][3],
                                r0, r2);
                        mma_f16(s[mi][2 * np + 1][0], s[mi][2 * np + 1][1],
                                s[mi][2 * np + 1][2], s[mi][2 * np + 1][3],
                                qf[mi][ks][0], qf[mi][ks][1], qf[mi][ks][2], qf[mi][ks][3],
                                r1, r3);
                    }
                }
            }

            uint32_t pe0[2][4], pe1[2][4];
#pragma unroll
            for (int mi = 0; mi < 2; mi++)
#pragma unroll
                for (int ni = 0; ni < 4; ni++) {
                    pe0[mi][ni] = ex2_h2(pack_f16(s[mi][ni][0], s[mi][ni][1]));
                    pe1[mi][ni] = ex2_h2(pack_f16(s[mi][ni][2], s[mi][ni][3]));
                }

#pragma unroll
            for (int t4 = 0; t4 < 2; t4++) {
#pragma unroll
                for (int vh = 0; vh < 2; vh++) {
                    uint32_t r0, r1, r2, r3;
                    ldsm4t(r0, r1, r2, r3,
                           vBase + (((key0 + 16 * t4 + l15) * VSR) + 16 * vh + lhi) * 2);
#pragma unroll
                    for (int mi = 0; mi < 2; mi++) {
                        mma_f16(o[mi][2 * vh][0], o[mi][2 * vh][1],
                                o[mi][2 * vh][2], o[mi][2 * vh][3],
                                pe0[mi][2 * t4], pe1[mi][2 * t4],
                                pe0[mi][2 * t4 + 1], pe1[mi][2 * t4 + 1],
                                r0, r1);
                        mma_f16(o[mi][2 * vh + 1][0], o[mi][2 * vh + 1][1],
                                o[mi][2 * vh + 1][2], o[mi][2 * vh + 1][3],
                                pe0[mi][2 * t4], pe1[mi][2 * t4],
                                pe0[mi][2 * t4 + 1], pe1[mi][2 * t4 + 1],
                                r2, r3);
                    }
                }
                {   // ones column
                    uint32_t r0, r1;
                    ldsm2t(r0, r1,
                           vBase + (((key0 + 16 * t4 + l15) * VSR) + 32) * 2);
#pragma unroll
                    for (int mi = 0; mi < 2; mi++)
                        mma_f16(ol[mi][0], ol[mi][1], ol[mi][2], ol[mi][3],
                                pe0[mi][2 * t4], pe1[mi][2 * t4],
                                pe0[mi][2 * t4 + 1], pe1[mi][2 * t4 + 1],
                                r0, r1);
                }
            }
        }
        if (++p == 3) p = 0;
    }

    const int b = bh >> 3;
    const int h = bh & 7;
#pragma unroll
    for (int mi = 0; mi < 2; mi++) {
        float l0 = __shfl_sync(0xffffffffu, ol[mi][0], lane & 28);
        float l1 = __shfl_sync(0xffffffffu, ol[mi][2], lane & 28);
        const int r0r = q0 + 32 * w + 16 * mi + g;
        float inv0 = 1.f / l0;
        float inv1 = 1.f / l1;
#pragma unroll
        for (int ni = 0; ni < 4; ni++) {
            int dk = 8 * ni + 2 * q4;
            size_t base0 = ((size_t)b * SS + r0r) * DD + h * DKK + dk;
            size_t base1 = ((size_t)b * SS + r0r + 8) * DD + h * DKK + dk;
            *(uint32_t*)&g_attn[base0] = pack_f16(o[mi][ni][0] * inv0, o[mi][ni][1] * inv0);
            *(uint32_t*)&g_attn[base1] = pack_f16(o[mi][ni][2] * inv1, o[mi][ni][3] * inv1);
        }
    }
    pdl_trigger();
}

// ============================================================================
// GEMM + residual + LayerNorm fused (#4, #6). Block 32(M) x 256(N), grid 256.
// PDL: weight (B) prefetch happens BEFORE the grid-dependency wait.
// Prologue groups: group0 = {B0,B1,A0}, group1 = {A1}; steady CP_WAIT(1).
// ============================================================================
template<bool FINAL>
__global__ __launch_bounds__(256, 2)
void gemm_ln(const __half* __restrict__ A, const __half* __restrict__ B,
             const __half* __restrict__ resH, const float* __restrict__ gw,
             const float* __restrict__ bw, float* __restrict__ outF,
             __half* __restrict__ outH, int K)
{
    __shared__ __half As[3][32 * ASR];
    __shared__ __half Bs[3][32 * BLR];
    __shared__ float sRed[32][4];
    __shared__ float qRed[32][4];

    const int t    = threadIdx.x;
    const int w    = t >> 5;
    const int lane = t & 31;
    const int g    = lane >> 2;
    const int q4   = lane & 3;
    const int wm   = w >> 2;
    const int wn   = w & 3;
    const int l15  = lane & 15;
    const int lhi  = (lane >> 4) << 3;
    const int row0 = blockIdx.x * 32;

    float acc[8][4];
#pragma unroll
    for (int ni = 0; ni < 8; ni++)
#pragma unroll
        for (int j = 0; j < 4; j++) acc[ni][j] = 0.f;

    auto issueA = [&](int st, int k0) {
        if (t < 128) {
            int r = t >> 2, c = (t & 3) << 3;
            cp16(smem_u32(&As[st][r * ASR + c]), &A[(size_t)(row0 + r) * K + k0 + c]);
        }
    };
    auto issueB = [&](int st, int k0) {
#pragma unroll
        for (int i = 0; i < 4; i++) {
            int id = t + i * 256;
            int r = id >> 5, c = (id & 31) << 3;
            cp16(smem_u32(&Bs[st][r * BLR + c]), &B[(size_t)(k0 + r) * DD + c]);
        }
    };

    // weights are independent of the predecessor kernel: prefetch pre-wait
    issueB(0, 0);
    issueB(1, 32);
    pdl_wait();              // A (and res) written by predecessor
    issueA(0, 0);  CP_COMMIT();   // group0 = {B0, B1, A0}
    issueA(1, 32); CP_COMMIT();   // group1 = {A1}

    int p = 0;
    const int nIter = K / 32;
    for (int it = 0; it < nIter; it++) {
        CP_WAIT(1);
        __syncthreads();
        int kn = (it + 2) * 32;
        if (kn < K) { int st = p + 2; if (st >= 3) st -= 3; issueA(st, kn); issueB(st, kn); }
        CP_COMMIT();

        const uint32_t aBase = smem_u32(As[p]);
        const uint32_t bBase = smem_u32(Bs[p]);
#pragma unroll
        for (int ks = 0; ks < 2; ks++) {
            uint32_t a[4];
            ldsm4(a[0], a[1], a[2], a[3],
                  aBase + (((16 * wm + l15) * ASR) + 16 * ks + lhi) * 2);
            uint32_t b[8][2];
#pragma unroll
            for (int np = 0; np < 4; np++) {
                uint32_t r0, r1, r2, r3;
                ldsm4t(r0, r1, r2, r3,
                       bBase + (((16 * ks + l15) * BLR) + 64 * wn + 16 * np + lhi) * 2);
                b[2 * np][0] = r0; b[2 * np][1] = r1;
                b[2 * np + 1][0] = r2; b[2 * np + 1][1] = r3;
            }
#pragma unroll
            for (int ni = 0; ni < 8; ni++)
                mma_f16(acc[ni][0], acc[ni][1], acc[ni][2], acc[ni][3],
                        a[0], a[1], a[2], a[3], b[ni][0], b[ni][1]);
        }
        if (++p == 3) p = 0;
    }

    // ---- epilogue: +res (f16), row stats, LN, store ----
#pragma unroll
    for (int half = 0; half < 2; half++) {
        int rl = 16 * wm + g + 8 * half;
        int rr = row0 + rl;
        float s = 0.f, ss = 0.f;
#pragma unroll
        for (int ni = 0; ni < 8; ni++) {
            int c = 64 * wn + 8 * ni + 2 * q4;
            float2 rv = __half22float2(*(const __half2*)&resH[(size_t)rr * DD + c]);
            float v0 = acc[ni][2 * half] + rv.x;
            float v1 = acc[ni][2 * half + 1] + rv.y;
            acc[ni][2 * half] = v0;
            acc[ni][2 * half + 1] = v1;
            s += v0 + v1;
            ss += v0 * v0 + v1 * v1;
        }
        s  += __shfl_xor_sync(0xffffffffu, s, 1);
        s  += __shfl_xor_sync(0xffffffffu, s, 2);
        ss += __shfl_xor_sync(0xffffffffu, ss, 1);
        ss += __shfl_xor_sync(0xffffffffu, ss, 2);
        if (q4 == 0) { sRed[rl][wn] = s; qRed[rl][wn] = ss; }
    }
    __syncthreads();

    float mu_[2], rs_[2];
#pragma unroll
    for (int half = 0; half < 2; half++) {
        int rl = 16 * wm + g + 8 * half;
        float tot  = sRed[rl][0] + sRed[rl][1] + sRed[rl][2] + sRed[rl][3];
        float tot2 = qRed[rl][0] + qRed[rl][1] + qRed[rl][2] + qRed[rl][3];
        float mu = tot * (1.f / 256.f);
        mu_[half] = mu;
        rs_[half] = rsqrtf(tot2 * (1.f / 256.f) - mu * mu + 1e-5f);
    }

#pragma unroll
    for (int half = 0; half < 2; half++) {
        int rr = row0 + 16 * wm + g + 8 * half;
        float mu = mu_[half], rstd = rs_[half];
#pragma unroll
        for (int ni = 0; ni < 8; ni++) {
            int c = 64 * wn + 8 * ni + 2 * q4;
            float2 gp = *(const float2*)&gw[c];
            float2 bp = *(const float2*)&bw[c];
            float o0 = (acc[ni][2 * half]     - mu) * rstd * gp.x + bp.x;
            float o1 = (acc[ni][2 * half + 1] - mu) * rstd * gp.y + bp.y;
            if (FINAL) *(float2*)&outF[(size_t)rr * DD + c] = make_float2(o0, o1);
            else       *(uint32_t*)&outH[(size_t)rr * DD + c] = pack_f16(o0, o1);
        }
    }
    pdl_trigger();
}

// ============================================================================
// GLU GEMM (#5): h = silu(A@W1) * (A@W2), block 128x64 dual-B, 3-stage ring.
// PDL: W1/W2 prefetch pre-wait; x1 loads post-wait.
// ============================================================================
__global__ __launch_bounds__(256, 2)
void gemm_glu(void)
{
    __shared__ __half As[3][128 * ASR];
    __shared__ __half Bs1[3][32 * GSR];
    __shared__ __half Bs2[3][32 * GSR];

    const int t    = threadIdx.x;
    const int w    = t >> 5;
    const int lane = t & 31;
    const int g    = lane >> 2;
    const int q4   = lane & 3;
    const int wm   = w >> 1;
    const int wn   = w & 1;
    const int l15  = lane & 15;
    const int lhi  = (lane >> 4) << 3;
    const int row0 = blockIdx.y * 128;
    const int col0 = blockIdx.x * 64;

    float ac1[2][4][4], ac2[2][4][4];
#pragma unroll
    for (int mi = 0; mi < 2; mi++)
#pragma unroll
        for (int ni = 0; ni < 4; ni++)
#pragma unroll
            for (int j = 0; j < 4; j++) { ac1[mi][ni][j] = 0.f; ac2[mi][ni][j] = 0.f; }

    auto issueA = [&](int st, int k0) {
#pragma unroll
        for (int i = 0; i < 2; i++) {
            int id = t + i * 256;
            int r = id >> 2, c = (id & 3) << 3;
            cp16(smem_u32(&As[st][r * ASR + c]), &g_x1[(size_t)(row0 + r) * DD + k0 + c]);
        }
    };
    auto issueB = [&](int st, int k0) {
        int r = t >> 3, c = (t & 7) << 3;
        cp16(smem_u32(&Bs1[st][r * GSR + c]), &g_w1[(size_t)(k0 + r) * FF + col0 + c]);
        cp16(smem_u32(&Bs2[st][r * GSR + c]), &g_w2[(size_t)(k0 + r) * FF + col0 + c]);
    };

    issueB(0, 0);
    issueB(1, 32);
    pdl_wait();              // x1 written by gemm_ln<false>
    issueA(0, 0);  CP_COMMIT();   // group0 = {B0, B1, A0}
    issueA(1, 32); CP_COMMIT();   // group1 = {A1}

    int p = 0;
    const int nIter = DD / 32;  // 8
    for (int it = 0; it < nIter; it++) {
        CP_WAIT(1);
        __syncthreads();
        int kn = (it + 2) * 32;
        if (kn < DD) { int st = p + 2; if (st >= 3) st -= 3; issueA(st, kn); issueB(st, kn); }
        CP_COMMIT();

        const uint32_t aBase  = smem_u32(As[p]);
        const uint32_t b1Base = smem_u32(Bs1[p]);
        const uint32_t b2Base = smem_u32(Bs2[p]);
#pragma unroll
        for (int ks = 0; ks < 2; ks++) {
            uint32_t a[2][4];
#pragma unroll
            for (int mi = 0; mi < 2; mi++)
                ldsm4(a[mi][0], a[mi][1], a[mi][2], a[mi][3],
                      aBase + (((32 * wm + 16 * mi + l15) * ASR) + 16 * ks + lhi) * 2);
            uint32_t b1[4][2], b2[4][2];
#pragma unroll
            for (int np = 0; np < 2; np++) {
                uint32_t r0, r1, r2, r3;
                ldsm4t(r0, r1, r2, r3,
                       b1Base + (((16 * ks + l15) * GSR) + 32 * wn + 16 * np + lhi) * 2);
                b1[2 * np][0] = r0; b1[2 * np][1] = r1;
                b1[2 * np + 1][0] = r2; b1[2 * np + 1][1] = r3;
                ldsm4t(r0, r1, r2, r3,
                       b2Base + (((16 * ks + l15) * GSR) + 32 * wn + 16 * np + lhi) * 2);
                b2[2 * np][0] = r0; b2[2 * np][1] = r1;
                b2[2 * np + 1][0] = r2; b2[2 * np + 1][1] = r3;
            }
#pragma unroll
            for (int mi = 0; mi < 2; mi++)
#pragma unroll
                for (int ni = 0; ni < 4; ni++) {
                    mma_f16(ac1[mi][ni][0], ac1[mi][ni][1], ac1[mi][ni][2], ac1[mi][ni][3],
                            a[mi][0], a[mi][1], a[mi][2], a[mi][3],
                            b1[ni][0], b1[ni][1]);
                    mma_f16(ac2[mi][ni][0], ac2[mi][ni][1], ac2[mi][ni][2], ac2[mi][ni][3],
                            a[mi][0], a[mi][1], a[mi][2], a[mi][3],
                            b2[ni][0], b2[ni][1]);
                }
        }
        if (++p == 3) p = 0;
    }

#pragma unroll
    for (int mi = 0; mi < 2; mi++) {
        int r = row0 + 32 * wm + 16 * mi + g;
#pragma unroll
        for (int ni = 0; ni < 4; ni++) {
            int c = col0 + 32 * wn + 8 * ni + 2 * q4;
#pragma unroll
            for (int half = 0; half < 2; half++) {
                int rr = r + half * 8;
                float u0 = ac1[mi][ni][2 * half], u1 = ac1[mi][ni][2 * half + 1];
                float v0 = ac2[mi][ni][2 * half], v1 = ac2[mi][ni][2 * half + 1];
                u0 = u0 / (1.f + ex2f(-L2E * u0));
                u1 = u1 / (1.f + ex2f(-L2E * u1));
                *(uint32_t*)&g_h[(size_t)rr * FF + c] = pack_f16(u0 * v0, u1 * v1);
            }
        }
    }
    pdl_trigger();
}

// ============================================================================
// Launch — PDL chain (kernels 2..6 opt into programmatic stream serialization)
// ============================================================================
extern "C" void kernel_launch(void* const* d_in, const int* in_sizes, int n_in,
                              void* d_out, int out_size)
{
    const float* x    = (const float*)d_in[0];
    const float* Wq   = (const float*)d_in[1];
    const float* Wk   = (const float*)d_in[2];
    const float* Wv   = (const float*)d_in[3];
    const float* Wo   = (const float*)d_in[4];
    const float* W1   = (const float*)d_in[5];
    const float* W2   = (const float*)d_in[6];
    const float* Wout = (const float*)d_in[7];
    const float* g1   = (const float*)d_in[8];
    const float* b1   = (const float*)d_in[9];
    const float* g2   = (const float*)d_in[10];
    const float* b2   = (const float*)d_in[11];

    __half *attn, *x1, *xh, *h, *wo_h, *wout_h;
    cudaGetSymbolAddress((void**)&attn,   g_attn);
    cudaGetSymbolAddress((void**)&x1,     g_x1);
    cudaGetSymbolAddress((void**)&h,      g_h);
    cudaGetSymbolAddress((void**)&xh,     g_xh);
    cudaGetSymbolAddress((void**)&wo_h,   g_wo);
    cudaGetSymbolAddress((void**)&wout_h, g_wout);

    cudaLaunchAttribute at[1];
    at[0].id = cudaLaunchAttributeProgrammaticStreamSerialization;
    at[0].val.programmaticStreamSerializationAllowed = 1;

    cudaLaunchConfig_t cfg{};
    cfg.blockDim = dim3(256, 1, 1);
    cfg.attrs    = at;
    cfg.numAttrs = 1;
    cfg.stream   = 0;

    // #1) cvt (plain launch; triggers dependents)
    cvt_all<<<3072, 256>>>(x, Wq, Wk, Wv, Wo, W1, W2, Wout);

    // #2) QKV
    cfg.gridDim = dim3(6, MTOT / 128, 1);
    cudaLaunchKernelEx(&cfg, gemm_qkv);

    // #3) attention
    cfg.gridDim = dim3(SS / 256, BB * HH, 1);
    cudaLaunchKernelEx(&cfg, attn_f16);

    // #4) attn @ Wo + x -> LN -> x1 (f16)
    cfg.gridDim = dim3(MTOT / 32, 1, 1);
    cudaLaunchKernelEx(&cfg, gemm_ln<false>,
                       (const __half*)attn, (const __half*)wo_h, (const __half*)xh,
                       g1, b1, (float*)nullptr, x1, (int)DD);

    // #5) GLU
    cfg.gridDim = dim3(FF / 64, MTOT / 128, 1);
    cudaLaunchKernelEx(&cfg, gemm_glu);

    // #6) h @ Wout + x1 -> LN -> out (fp32)
    cfg.gridDim = dim3(MTOT / 32, 1, 1);
    cudaLaunchKernelEx(&cfg, gemm_ln<true>,
                       (const __half*)h, (const __half*)wout_h, (const __half*)x1,
                       g2, b2, (float*)d_out, (__half*)nullptr, (int)FF);
}